// round 9
// baseline (speedup 1.0000x reference)
#include <cuda_runtime.h>
#include <cuda_bf16.h>
#include <cstdint>

// Problem shape (fixed by dataset)
#define N_MAX   50000
#define E_MAX   800000
#define EMB     128
#define KTOT    256     // NF + EMB

// ---------------- device scratch (static: no runtime allocation) -----------
__device__ int      g_deg[N_MAX];
__device__ int      g_off[N_MAX + 1];
__device__ int      g_rank[E_MAX];
__device__ int      g_eidx[E_MAX];
__device__ float4   g_aggr4[N_MAX * 32];        // [N][32] float4 = h_aggr
__device__ uint32_t g_Whi[EMB * (KTOT / 2)];    // [128][128] bf16x2 words
__device__ uint32_t g_Wlo[EMB * (KTOT / 2)];

// ============================ CSR build ====================================
__global__ void zero_deg_kernel(int n) {
    int i = blockIdx.x * blockDim.x + threadIdx.x;
    if (i < n) g_deg[i] = 0;
}

__global__ void hist_rank_kernel(const int* __restrict__ dst, int e) {
    int i = blockIdx.x * blockDim.x + threadIdx.x;
    if (i < e) g_rank[i] = atomicAdd(&g_deg[dst[i]], 1);
}

__global__ void scan_kernel(int n) {
    const int T = 1024;
    int tid  = threadIdx.x;
    int lane = tid & 31;
    int wid  = tid >> 5;
    int C = (n + T - 1) / T;
    int s = tid * C;
    int e = min(s + C, n);

    int sum = 0;
    for (int i = s; i < e; i++) sum += g_deg[i];

    int v = sum;
    #pragma unroll
    for (int d = 1; d < 32; d <<= 1) {
        int t = __shfl_up_sync(0xffffffffu, v, d);
        if (lane >= d) v += t;
    }
    __shared__ int wsum[32];
    if (lane == 31) wsum[wid] = v;
    __syncthreads();
    if (wid == 0) {
        int w = wsum[lane];
        #pragma unroll
        for (int d = 1; d < 32; d <<= 1) {
            int t = __shfl_up_sync(0xffffffffu, w, d);
            if (lane >= d) w += t;
        }
        wsum[lane] = w;
    }
    __syncthreads();

    int excl = (v - sum) + (wid > 0 ? wsum[wid - 1] : 0);
    int run = excl;
    for (int i = s; i < e; i++) {
        g_off[i] = run;
        run += g_deg[i];
    }
    if (e == n) g_off[n] = run;
}

__global__ void scatter_kernel(const int* __restrict__ dst, int e) {
    int i = blockIdx.x * blockDim.x + threadIdx.x;
    if (i < e) g_eidx[g_off[dst[i]] + g_rank[i]] = i;
}

// ===================== bf16 split helpers ==================================
__device__ __forceinline__ uint32_t pk_bf2(float lo, float hi) {
    uint32_t r;
    asm("cvt.rn.bf16x2.f32 %0, %1, %2;" : "=r"(r) : "f"(hi), "f"(lo));
    return r;
}
__device__ __forceinline__ float2 unpk_bf2(uint32_t w) {
    __nv_bfloat162 b = *reinterpret_cast<__nv_bfloat162*>(&w);
    return __bfloat1622float2(b);
}
__device__ __forceinline__ void split2(float a, float b,
                                       uint32_t& hi, uint32_t& lo) {
    hi = pk_bf2(a, b);
    float2 f = unpk_bf2(hi);
    lo = pk_bf2(a - f.x, b - f.y);
}

// --------------- W pre-conversion: f32 -> bf16 hi/lo words -----------------
__global__ void cvt_w_kernel(const float2* __restrict__ W2) {
    int i = blockIdx.x * blockDim.x + threadIdx.x;
    if (i >= EMB * (KTOT / 2)) return;
    float2 v = W2[i];
    uint32_t hi, lo;
    split2(v.x, v.y, hi, lo);
    g_Whi[i] = hi;
    g_Wlo[i] = lo;
}

// ===================== HMMA GEMM tile (half-K) ==============================
// 64 nodes x 128 cols over one K half (koff = 0 or 128).
// EPI=0: store raw partial. EPI=1: += partial, + bias, relu.
// R7-validated fragment layout; smem rows 36 words -> conflict-free LDS.

#define GM       64
#define ROWW     36
#define SA_W     (GM * ROWW)               // 2304 words
#define SW_W     (EMB * ROWW)              // 4608 words
#define GSMEM_W  (2 * SA_W + 2 * SW_W)
#define GSMEM_B  (GSMEM_W * 4)             // 55296 B

__device__ __forceinline__ void mma_bf16(float4& d,
    uint32_t a0, uint32_t a1, uint32_t a2, uint32_t a3,
    uint32_t b0, uint32_t b1) {
    asm("mma.sync.aligned.m16n8k16.row.col.f32.bf16.bf16.f32 "
        "{%0,%1,%2,%3}, {%4,%5,%6,%7}, {%8,%9}, {%0,%1,%2,%3};"
        : "+f"(d.x), "+f"(d.y), "+f"(d.z), "+f"(d.w)
        : "r"(a0), "r"(a1), "r"(a2), "r"(a3), "r"(b0), "r"(b1));
}

template<int EPI>
__device__ __forceinline__ void gemm_tile(const float4* __restrict__ A4,
                                          const float*  __restrict__ bias,
                                          float* __restrict__ out,
                                          int n, int nb, int koff,
                                          uint32_t* sm) {
    uint32_t* sAh = sm;
    uint32_t* sAl = sm + SA_W;
    uint32_t* sWh = sm + 2 * SA_W;
    uint32_t* sWl = sm + 2 * SA_W + SW_W;

    int tid  = threadIdx.x;
    int warp = tid >> 5;
    int lane = tid & 31;
    int g    = lane >> 2;
    int tig  = lane & 3;
    int mw   = warp >> 2;
    int nw   = warp & 3;
    int m0   = mw * 32;
    int n0   = nw * 32;

    float4 acc[2][4];
    #pragma unroll
    for (int mt = 0; mt < 2; mt++)
        #pragma unroll
        for (int nt = 0; nt < 4; nt++)
            acc[mt][nt] = make_float4(0.f, 0.f, 0.f, 0.f);

    for (int kc = 0; kc < 128; kc += 64) {
        __syncthreads();
        // ---- stage A chunk (f32 -> bf16 hi/lo) ----
        #pragma unroll
        for (int f = tid; f < GM * 16; f += 256) {
            int m = f >> 4;
            int q = f & 15;
            int node = nb + m;
            float4 v = make_float4(0.f, 0.f, 0.f, 0.f);
            if (node < n) v = A4[(size_t)node * 32 + (kc >> 2) + q];
            uint32_t h0, l0, h1, l1;
            split2(v.x, v.y, h0, l0);
            split2(v.z, v.w, h1, l1);
            int w = m * ROWW + q * 2;
            *reinterpret_cast<uint2*>(sAh + w) = make_uint2(h0, h1);
            *reinterpret_cast<uint2*>(sAl + w) = make_uint2(l0, l1);
        }
        // ---- stage W chunk (pre-converted) ----
        #pragma unroll
        for (int f = tid; f < EMB * 8; f += 256) {
            int c = f >> 3;
            int q = f & 7;
            int src  = c * (KTOT / 2) + ((koff + kc) >> 1) + q * 4;
            int dstw = c * ROWW + q * 4;
            *reinterpret_cast<uint4*>(sWh + dstw) =
                *reinterpret_cast<const uint4*>(g_Whi + src);
            *reinterpret_cast<uint4*>(sWl + dstw) =
                *reinterpret_cast<const uint4*>(g_Wlo + src);
        }
        __syncthreads();

        #pragma unroll
        for (int s = 0; s < 4; s++) {
            int so = s * 8 + tig;

            uint32_t ah[2][4], al[2][4];
            #pragma unroll
            for (int mt = 0; mt < 2; mt++) {
                int r0 = (m0 + mt * 16 + g) * ROWW;
                int r1 = r0 + 8 * ROWW;
                ah[mt][0] = sAh[r0 + so];
                ah[mt][1] = sAh[r1 + so];
                ah[mt][2] = sAh[r0 + so + 4];
                ah[mt][3] = sAh[r1 + so + 4];
                al[mt][0] = sAl[r0 + so];
                al[mt][1] = sAl[r1 + so];
                al[mt][2] = sAl[r0 + so + 4];
                al[mt][3] = sAl[r1 + so + 4];
            }
            uint32_t bh[4][2], bl[4][2];
            #pragma unroll
            for (int nt = 0; nt < 4; nt++) {
                int rn = (n0 + nt * 8 + g) * ROWW;
                bh[nt][0] = sWh[rn + so];
                bh[nt][1] = sWh[rn + so + 4];
                bl[nt][0] = sWl[rn + so];
                bl[nt][1] = sWl[rn + so + 4];
            }
            #pragma unroll
            for (int mt = 0; mt < 2; mt++)
                #pragma unroll
                for (int nt = 0; nt < 4; nt++) {
                    mma_bf16(acc[mt][nt],
                             ah[mt][0], ah[mt][1], ah[mt][2], ah[mt][3],
                             bh[nt][0], bh[nt][1]);
                    mma_bf16(acc[mt][nt],
                             ah[mt][0], ah[mt][1], ah[mt][2], ah[mt][3],
                             bl[nt][0], bl[nt][1]);
                    mma_bf16(acc[mt][nt],
                             al[mt][0], al[mt][1], al[mt][2], al[mt][3],
                             bh[nt][0], bh[nt][1]);
                }
        }
    }

    // ---- epilogue ----
    #pragma unroll
    for (int mt = 0; mt < 2; mt++) {
        int r0 = nb + m0 + mt * 16 + g;
        int r1 = r0 + 8;
        #pragma unroll
        for (int nt = 0; nt < 4; nt++) {
            int col = n0 + nt * 8 + tig * 2;
            float4 a = acc[mt][nt];
            if (EPI == 1) {
                float bx = __ldg(bias + col);
                float by = __ldg(bias + col + 1);
                if (r0 < n) {
                    float* p = out + (size_t)r0 * EMB + col;
                    float2 pr = *reinterpret_cast<const float2*>(p);
                    *reinterpret_cast<float2*>(p) =
                        make_float2(fmaxf(a.x + pr.x + bx, 0.f),
                                    fmaxf(a.y + pr.y + by, 0.f));
                }
                if (r1 < n) {
                    float* p = out + (size_t)r1 * EMB + col;
                    float2 pr = *reinterpret_cast<const float2*>(p);
                    *reinterpret_cast<float2*>(p) =
                        make_float2(fmaxf(a.z + pr.x + bx, 0.f),
                                    fmaxf(a.w + pr.y + by, 0.f));
                }
            } else {
                if (r0 < n)
                    *reinterpret_cast<float2*>(out + (size_t)r0 * EMB + col) =
                        make_float2(a.x, a.y);
                if (r1 < n)
                    *reinterpret_cast<float2*>(out + (size_t)r1 * EMB + col) =
                        make_float2(a.z, a.w);
            }
        }
    }
}

// ============== mixed kernel: gather blocks + GEMM1 tiles ==================
// r % 9 == 8 -> GEMM1 tile (x @ Wx^T -> raw partial in out), else gather
// block (one warp per node). Roles use disjoint pipes (DRAM/LSU vs
// tensor/LDS) and co-reside on SMs -> overlap.
__global__ void __launch_bounds__(256, 3)
mixed_kernel(const float4* __restrict__ h4,
             const float4* __restrict__ x4,
             float* __restrict__ out, int n) {
    extern __shared__ uint32_t sm[];
    int r = blockIdx.x;

    if ((r % 9) == 8) {
        gemm_tile<0>(x4, nullptr, out, n, (r / 9) * GM, 0, sm);
        return;
    }

    int gb   = r - r / 9;
    int warp = threadIdx.x >> 5;
    int lane = threadIdx.x & 31;
    int node = gb * 8 + warp;
    if (node >= n) return;

    int s = g_off[node];
    int e = g_off[node + 1];
    float4 a = make_float4(0.f, 0.f, 0.f, 0.f);
    int j = s;
    for (; j + 8 <= e; j += 8) {
        float4 v[8];
        #pragma unroll
        for (int u = 0; u < 8; u++) {
            int ei = __ldg(g_eidx + j + u);
            v[u] = __ldg(h4 + (size_t)ei * 32 + lane);
        }
        #pragma unroll
        for (int u = 0; u < 8; u++) {
            a.x += v[u].x; a.y += v[u].y; a.z += v[u].z; a.w += v[u].w;
        }
    }
    if (j + 4 <= e) {
        float4 v[4];
        #pragma unroll
        for (int u = 0; u < 4; u++) {
            int ei = __ldg(g_eidx + j + u);
            v[u] = __ldg(h4 + (size_t)ei * 32 + lane);
        }
        #pragma unroll
        for (int u = 0; u < 4; u++) {
            a.x += v[u].x; a.y += v[u].y; a.z += v[u].z; a.w += v[u].w;
        }
        j += 4;
    }
    for (; j < e; j++) {
        int ei = __ldg(g_eidx + j);
        float4 v0 = __ldg(h4 + (size_t)ei * 32 + lane);
        a.x += v0.x; a.y += v0.y; a.z += v0.z; a.w += v0.w;
    }
    g_aggr4[(size_t)node * 32 + lane] = a;
}

// ============== GEMM2: out = relu(partial + aggr @ Wh^T + b) ===============
__global__ void __launch_bounds__(256, 3)
gemm2_kernel(const float* __restrict__ bias,
             float* __restrict__ out, int n) {
    extern __shared__ uint32_t sm[];
    gemm_tile<1>(g_aggr4, bias, out, n, blockIdx.x * GM, 128, sm);
}

// ---------------- launch ----------------------------------------------------
extern "C" void kernel_launch(void* const* d_in, const int* in_sizes, int n_in,
                              void* d_out, int out_size) {
    const float* h        = (const float*)d_in[0];   // [E, 128]
    const float* x        = (const float*)d_in[1];   // [N, 128]
    const int*   edge_dst = (const int*)  d_in[2];   // [E] int32
    const float* W        = (const float*)d_in[3];   // [128, 256]
    const float* b        = (const float*)d_in[4];   // [128]
    float*       out      = (float*)d_out;           // [N, 128]

    int E = in_sizes[2];
    int N = in_sizes[1] / EMB;

    cudaFuncSetAttribute(mixed_kernel,
                         cudaFuncAttributeMaxDynamicSharedMemorySize, GSMEM_B);
    cudaFuncSetAttribute(gemm2_kernel,
                         cudaFuncAttributeMaxDynamicSharedMemorySize, GSMEM_B);

    int gemmBlocks = (N + GM - 1) / GM;      // 782
    int combined   = gemmBlocks * 9;         // 1-in-9 are GEMM1 tiles

    zero_deg_kernel<<<(N + 255) / 256, 256>>>(N);
    hist_rank_kernel<<<(E + 255) / 256, 256>>>(edge_dst, E);
    scan_kernel<<<1, 1024>>>(N);
    scatter_kernel<<<(E + 255) / 256, 256>>>(edge_dst, E);
    cvt_w_kernel<<<(EMB * (KTOT / 2) + 255) / 256, 256>>>(
        reinterpret_cast<const float2*>(W));
    mixed_kernel<<<combined, 256, GSMEM_B>>>(
        reinterpret_cast<const float4*>(h),
        reinterpret_cast<const float4*>(x),
        out, N);
    gemm2_kernel<<<gemmBlocks, 256, GSMEM_B>>>(b, out, N);
}

// round 10
// speedup vs baseline: 1.1215x; 1.1215x over previous
#include <cuda_runtime.h>
#include <cuda_bf16.h>
#include <cstdint>

// Problem shape (fixed by dataset)
#define N_MAX   50000
#define E_MAX   800000
#define EMB     128
#define KTOT    256     // NF + EMB

// ---------------- device scratch (static: no runtime allocation) -----------
__device__ int      g_deg[N_MAX];
__device__ int      g_off[N_MAX + 1];
__device__ int      g_rank[E_MAX];
__device__ int      g_eidx[E_MAX];
__device__ uint32_t g_Ahi[N_MAX * 64];          // [N][64] bf16x2 words (hi)
__device__ uint32_t g_Alo[N_MAX * 64];          // [N][64] bf16x2 words (lo)
__device__ uint32_t g_Whi[EMB * (KTOT / 2)];    // [128][128] bf16x2 words
__device__ uint32_t g_Wlo[EMB * (KTOT / 2)];

// ===================== bf16 split helpers ==================================
__device__ __forceinline__ uint32_t pk_bf2(float lo, float hi) {
    uint32_t r;
    asm("cvt.rn.bf16x2.f32 %0, %1, %2;" : "=r"(r) : "f"(hi), "f"(lo));
    return r;
}
__device__ __forceinline__ float2 unpk_bf2(uint32_t w) {
    __nv_bfloat162 b = *reinterpret_cast<__nv_bfloat162*>(&w);
    return __bfloat1622float2(b);
}
__device__ __forceinline__ void split2(float a, float b,
                                       uint32_t& hi, uint32_t& lo) {
    hi = pk_bf2(a, b);
    float2 f = unpk_bf2(hi);
    lo = pk_bf2(a - f.x, b - f.y);
}

// ============== prep: zero degree counters + W f32->bf16 hi/lo =============
__global__ void prep_kernel(const float2* __restrict__ W2, int n) {
    int i = blockIdx.x * blockDim.x + threadIdx.x;
    if (i < n) g_deg[i] = 0;
    if (i < EMB * (KTOT / 2)) {
        float2 v = W2[i];
        uint32_t hi, lo;
        split2(v.x, v.y, hi, lo);
        g_Whi[i] = hi;
        g_Wlo[i] = lo;
    }
}

// ============================ CSR build ====================================
__global__ void hist_rank_kernel(const int* __restrict__ dst, int e) {
    int i = blockIdx.x * blockDim.x + threadIdx.x;
    if (i < e) g_rank[i] = atomicAdd(&g_deg[dst[i]], 1);
}

__global__ void scan_kernel(int n) {
    const int T = 1024;
    int tid  = threadIdx.x;
    int lane = tid & 31;
    int wid  = tid >> 5;
    int C = (n + T - 1) / T;
    int s = tid * C;
    int e = min(s + C, n);

    int sum = 0;
    for (int i = s; i < e; i++) sum += g_deg[i];

    int v = sum;
    #pragma unroll
    for (int d = 1; d < 32; d <<= 1) {
        int t = __shfl_up_sync(0xffffffffu, v, d);
        if (lane >= d) v += t;
    }
    __shared__ int wsum[32];
    if (lane == 31) wsum[wid] = v;
    __syncthreads();
    if (wid == 0) {
        int w = wsum[lane];
        #pragma unroll
        for (int d = 1; d < 32; d <<= 1) {
            int t = __shfl_up_sync(0xffffffffu, w, d);
            if (lane >= d) w += t;
        }
        wsum[lane] = w;
    }
    __syncthreads();

    int excl = (v - sum) + (wid > 0 ? wsum[wid - 1] : 0);
    int run = excl;
    for (int i = s; i < e; i++) {
        g_off[i] = run;
        run += g_deg[i];
    }
    if (e == n) g_off[n] = run;
}

__global__ void scatter_kernel(const int* __restrict__ dst, int e) {
    int i = blockIdx.x * blockDim.x + threadIdx.x;
    if (i < e) g_eidx[g_off[dst[i]] + g_rank[i]] = i;
}

// --------------------------- gather kernel ---------------------------------
// One warp per node, 16B per lane (512B row per edge), unroll 8 for MLP.
// Output written directly as bf16 hi/lo (halves aggr traffic; GEMM stages
// it without conversion).
__global__ void __launch_bounds__(256)
gather_kernel(const float4* __restrict__ h4, int n) {
    int node = blockIdx.x * 8 + (threadIdx.x >> 5);
    int lane = threadIdx.x & 31;
    if (node >= n) return;

    int s = g_off[node];
    int e = g_off[node + 1];
    float4 a = make_float4(0.f, 0.f, 0.f, 0.f);
    int j = s;
    for (; j + 8 <= e; j += 8) {
        float4 v[8];
        #pragma unroll
        for (int u = 0; u < 8; u++) {
            int ei = __ldg(g_eidx + j + u);
            v[u] = __ldg(h4 + (size_t)ei * 32 + lane);
        }
        #pragma unroll
        for (int u = 0; u < 8; u++) {
            a.x += v[u].x; a.y += v[u].y; a.z += v[u].z; a.w += v[u].w;
        }
    }
    if (j + 4 <= e) {
        float4 v[4];
        #pragma unroll
        for (int u = 0; u < 4; u++) {
            int ei = __ldg(g_eidx + j + u);
            v[u] = __ldg(h4 + (size_t)ei * 32 + lane);
        }
        #pragma unroll
        for (int u = 0; u < 4; u++) {
            a.x += v[u].x; a.y += v[u].y; a.z += v[u].z; a.w += v[u].w;
        }
        j += 4;
    }
    for (; j < e; j++) {
        int ei = __ldg(g_eidx + j);
        float4 v0 = __ldg(h4 + (size_t)ei * 32 + lane);
        a.x += v0.x; a.y += v0.y; a.z += v0.z; a.w += v0.w;
    }

    uint32_t h0, l0, h1, l1;
    split2(a.x, a.y, h0, l0);
    split2(a.z, a.w, h1, l1);
    size_t base = (size_t)node * 64 + lane * 2;
    *reinterpret_cast<uint2*>(g_Ahi + base) = make_uint2(h0, h1);
    *reinterpret_cast<uint2*>(g_Alo + base) = make_uint2(l0, l1);
}

// ===================== HMMA GEMM: out = relu(q @ W^T + b) ==================
// CTA = 64 nodes x 128 cols, 256 threads (8 warps: 2m x 4n, warp 32x32).
// K=256 in 4 chunks of 64. A = x (f32, split in-CTA) for k<128, pre-split
// aggr bf16 for k>=128. Split-precision: D += Ah*Wh + Ah*Wl + Al*Wh.
// smem rows padded to 36 words -> conflict-free fragment LDS.

#define GM       64
#define ROWW     36
#define SA_W     (GM * ROWW)               // 2304 words
#define SW_W     (EMB * ROWW)              // 4608 words
#define GSMEM_W  (2 * SA_W + 2 * SW_W + EMB)
#define GSMEM_B  (GSMEM_W * 4)             // 55808 B

__device__ __forceinline__ void mma_bf16(float4& d,
    uint32_t a0, uint32_t a1, uint32_t a2, uint32_t a3,
    uint32_t b0, uint32_t b1) {
    asm("mma.sync.aligned.m16n8k16.row.col.f32.bf16.bf16.f32 "
        "{%0,%1,%2,%3}, {%4,%5,%6,%7}, {%8,%9}, {%0,%1,%2,%3};"
        : "+f"(d.x), "+f"(d.y), "+f"(d.z), "+f"(d.w)
        : "r"(a0), "r"(a1), "r"(a2), "r"(a3), "r"(b0), "r"(b1));
}

__global__ void __launch_bounds__(256, 2)
gemm_kernel(const float4* __restrict__ x4,
            const float*  __restrict__ bias,
            float* __restrict__ out, int n) {
    extern __shared__ uint32_t sm[];
    uint32_t* sAh = sm;
    uint32_t* sAl = sm + SA_W;
    uint32_t* sWh = sm + 2 * SA_W;
    uint32_t* sWl = sm + 2 * SA_W + SW_W;
    float*    sB  = reinterpret_cast<float*>(sm + 2 * SA_W + 2 * SW_W);

    int tid  = threadIdx.x;
    int warp = tid >> 5;
    int lane = tid & 31;
    int g    = lane >> 2;
    int tig  = lane & 3;
    int mw   = warp >> 2;
    int nw   = warp & 3;
    int m0   = mw * 32;
    int n0   = nw * 32;
    int nb   = blockIdx.x * GM;

    if (tid < EMB) sB[tid] = bias[tid];

    float4 acc[2][4];
    #pragma unroll
    for (int mt = 0; mt < 2; mt++)
        #pragma unroll
        for (int nt = 0; nt < 4; nt++)
            acc[mt][nt] = make_float4(0.f, 0.f, 0.f, 0.f);

    for (int kc = 0; kc < KTOT; kc += 64) {
        __syncthreads();
        if (kc < 128) {
            // ---- stage A from x (f32 -> bf16 hi/lo) ----
            #pragma unroll
            for (int f = tid; f < GM * 16; f += 256) {
                int m = f >> 4;
                int q = f & 15;
                int node = nb + m;
                float4 v = make_float4(0.f, 0.f, 0.f, 0.f);
                if (node < n) v = x4[(size_t)node * 32 + (kc >> 2) + q];
                uint32_t h0, l0, h1, l1;
                split2(v.x, v.y, h0, l0);
                split2(v.z, v.w, h1, l1);
                int w = m * ROWW + q * 2;
                *reinterpret_cast<uint2*>(sAh + w) = make_uint2(h0, h1);
                *reinterpret_cast<uint2*>(sAl + w) = make_uint2(l0, l1);
            }
        } else {
            // ---- stage A from pre-split aggr (straight copy) ----
            int ko2 = (kc - 128) >> 1;       // word base: 0 or 32
            #pragma unroll
            for (int f = tid; f < GM * 16; f += 256) {
                int m = f >> 4;
                int q = f & 15;
                int node = nb + m;
                uint2 h = make_uint2(0u, 0u);
                uint2 l = make_uint2(0u, 0u);
                if (node < n) {
                    size_t src = (size_t)node * 64 + ko2 + q * 2;
                    h = *reinterpret_cast<const uint2*>(g_Ahi + src);
                    l = *reinterpret_cast<const uint2*>(g_Alo + src);
                }
                int w = m * ROWW + q * 2;
                *reinterpret_cast<uint2*>(sAh + w) = h;
                *reinterpret_cast<uint2*>(sAl + w) = l;
            }
        }
        // ---- stage W chunk (pre-converted) ----
        #pragma unroll
        for (int f = tid; f < EMB * 8; f += 256) {
            int c = f >> 3;
            int q = f & 7;
            int src  = c * (KTOT / 2) + (kc >> 1) + q * 4;
            int dstw = c * ROWW + q * 4;
            *reinterpret_cast<uint4*>(sWh + dstw) =
                *reinterpret_cast<const uint4*>(g_Whi + src);
            *reinterpret_cast<uint4*>(sWl + dstw) =
                *reinterpret_cast<const uint4*>(g_Wlo + src);
        }
        __syncthreads();

        // ---- 4 k16 steps ----
        #pragma unroll
        for (int s = 0; s < 4; s++) {
            int so = s * 8 + tig;

            uint32_t ah[2][4], al[2][4];
            #pragma unroll
            for (int mt = 0; mt < 2; mt++) {
                int r0 = (m0 + mt * 16 + g) * ROWW;
                int r1 = r0 + 8 * ROWW;
                ah[mt][0] = sAh[r0 + so];
                ah[mt][1] = sAh[r1 + so];
                ah[mt][2] = sAh[r0 + so + 4];
                ah[mt][3] = sAh[r1 + so + 4];
                al[mt][0] = sAl[r0 + so];
                al[mt][1] = sAl[r1 + so];
                al[mt][2] = sAl[r0 + so + 4];
                al[mt][3] = sAl[r1 + so + 4];
            }
            uint32_t bh[4][2], bl[4][2];
            #pragma unroll
            for (int nt = 0; nt < 4; nt++) {
                int rn = (n0 + nt * 8 + g) * ROWW;
                bh[nt][0] = sWh[rn + so];
                bh[nt][1] = sWh[rn + so + 4];
                bl[nt][0] = sWl[rn + so];
                bl[nt][1] = sWl[rn + so + 4];
            }
            #pragma unroll
            for (int mt = 0; mt < 2; mt++)
                #pragma unroll
                for (int nt = 0; nt < 4; nt++) {
                    mma_bf16(acc[mt][nt],
                             ah[mt][0], ah[mt][1], ah[mt][2], ah[mt][3],
                             bh[nt][0], bh[nt][1]);
                    mma_bf16(acc[mt][nt],
                             ah[mt][0], ah[mt][1], ah[mt][2], ah[mt][3],
                             bl[nt][0], bl[nt][1]);
                    mma_bf16(acc[mt][nt],
                             al[mt][0], al[mt][1], al[mt][2], al[mt][3],
                             bh[nt][0], bh[nt][1]);
                }
        }
    }

    // ---- epilogue: bias + relu + store ----
    #pragma unroll
    for (int mt = 0; mt < 2; mt++) {
        int r0 = nb + m0 + mt * 16 + g;
        int r1 = r0 + 8;
        #pragma unroll
        for (int nt = 0; nt < 4; nt++) {
            int col = n0 + nt * 8 + tig * 2;
            float bx = sB[col], by = sB[col + 1];
            float4 a = acc[mt][nt];
            if (r0 < n) {
                float2 v = make_float2(fmaxf(a.x + bx, 0.f),
                                       fmaxf(a.y + by, 0.f));
                *reinterpret_cast<float2*>(out + (size_t)r0 * EMB + col) = v;
            }
            if (r1 < n) {
                float2 v = make_float2(fmaxf(a.z + bx, 0.f),
                                       fmaxf(a.w + by, 0.f));
                *reinterpret_cast<float2*>(out + (size_t)r1 * EMB + col) = v;
            }
        }
    }
}

// ---------------- launch ----------------------------------------------------
extern "C" void kernel_launch(void* const* d_in, const int* in_sizes, int n_in,
                              void* d_out, int out_size) {
    const float* h        = (const float*)d_in[0];   // [E, 128]
    const float* x        = (const float*)d_in[1];   // [N, 128]
    const int*   edge_dst = (const int*)  d_in[2];   // [E] int32
    const float* W        = (const float*)d_in[3];   // [128, 256]
    const float* b        = (const float*)d_in[4];   // [128]
    float*       out      = (float*)d_out;           // [N, 128]

    int E = in_sizes[2];
    int N = in_sizes[1] / EMB;

    cudaFuncSetAttribute(gemm_kernel,
                         cudaFuncAttributeMaxDynamicSharedMemorySize, GSMEM_B);

    int prepN = (N > EMB * (KTOT / 2)) ? N : EMB * (KTOT / 2);

    prep_kernel<<<(prepN + 255) / 256, 256>>>(
        reinterpret_cast<const float2*>(W), N);
    hist_rank_kernel<<<(E + 255) / 256, 256>>>(edge_dst, E);
    scan_kernel<<<1, 1024>>>(N);
    scatter_kernel<<<(E + 255) / 256, 256>>>(edge_dst, E);
    gather_kernel<<<(N + 7) / 8, 256>>>(
        reinterpret_cast<const float4*>(h), N);
    gemm_kernel<<<(N + GM - 1) / GM, 256, GSMEM_B>>>(
        reinterpret_cast<const float4*>(x), b, out, N);
}